// round 13
// baseline (speedup 1.0000x reference)
#include <cuda_runtime.h>
#include <cuda_bf16.h>
#include <cstdint>

// ---------------------------------------------------------------------------
// DeepAttention: 3x multiplicative attention + BiLSTM.
// GEMMs via mma.sync HMMA bf16 (hi/lo split, 3-term), k32 stages / 3-stage
// cp.async pipeline sized for 2 CTAs per SM (4 warps/SMSP latency hiding).
// LSTM: persistent kernel, atomicAdd+release grid barrier (round-4 form).
// ---------------------------------------------------------------------------

#define AL16 __align__(16)

#define NB 32
#define LL 512
#define ATTP 1344      // 1324 padded to 21*64
#define ND3 768        // 3 heads * 256
#define RNNIN 2560
#define NGATE 2048
#define HID 256
#define LSTM_NB 128

typedef __nv_bfloat16 bf16;

// ------------------------------- scratch -----------------------------------
__device__ AL16 bf16  g_xatt_hi[2 * NB * LL * ATTP];
__device__ AL16 bf16  g_xatt_lo[2 * NB * LL * ATTP];
__device__ AL16 bf16  g_U_hi[ND3 * ATTP];
__device__ AL16 bf16  g_U_lo[ND3 * ATTP];
__device__ AL16 float g_dvec[ND3];
__device__ AL16 bf16  g_r_hi[2 * NB * LL * ND3];
__device__ AL16 bf16  g_r_lo[2 * NB * LL * ND3];
__device__ AL16 float g_scores[3 * NB * LL * LL];
__device__ AL16 bf16  g_al_hi[3 * NB * LL * LL];
__device__ AL16 bf16  g_al_lo[3 * NB * LL * LL];
__device__ AL16 bf16  g_x3t_hi[3 * NB * LL * LL];
__device__ AL16 bf16  g_x3t_lo[3 * NB * LL * LL];
__device__ AL16 bf16  g_x1_hi[NB * LL * RNNIN];
__device__ AL16 bf16  g_x1_lo[NB * LL * RNNIN];
__device__ AL16 bf16  g_W_hi[NGATE * RNNIN];
__device__ AL16 bf16  g_W_lo[NGATE * RNNIN];
__device__ AL16 float g_bias[NGATE];
__device__ AL16 float g_gates[NB * LL * NGATE];
__device__ AL16 float g_h[2][2][NB][HID];
__device__ unsigned g_count;      // grid barrier (monotonic)
__device__ unsigned g_release;

__device__ __forceinline__ void bsplit(float v, bf16& h, bf16& l) {
    h = __float2bfloat16(v);
    l = __float2bfloat16(v - __bfloat162float(h));
}

__device__ __forceinline__ void bsplit2pack(float a, float b, uint32_t& hi, uint32_t& lo) {
    bf16 ha, la, hb, lb;
    bsplit(a, ha, la); bsplit(b, hb, lb);
    __nv_bfloat162 H; H.x = ha; H.y = hb;
    __nv_bfloat162 L; L.x = la; L.y = lb;
    hi = *reinterpret_cast<uint32_t*>(&H);
    lo = *reinterpret_cast<uint32_t*>(&L);
}

// ----------------------------- build kernels (vectorized) ------------------
__global__ void k_build_xatt(const float* __restrict__ x1w, const float* __restrict__ x1a0,
                             const float* __restrict__ x1a1, const float* __restrict__ x2w,
                             const float* __restrict__ x2a0, const float* __restrict__ x2a1) {
    int idx = blockIdx.x * blockDim.x + threadIdx.x;
    const int total4 = 2 * NB * LL * (ATTP / 4);
    if (idx >= total4) return;
    int row = idx / (ATTP / 4);
    int col = (idx - row * (ATTP / 4)) * 4;
    int src = row & 16383;
    bool is2 = row >= 16384;
    float4 v = make_float4(0.f, 0.f, 0.f, 0.f);
    if (col < 300)        v = *reinterpret_cast<const float4*>(&(is2 ? x2w  : x1w )[src * 300 + col]);
    else if (col < 812)   v = *reinterpret_cast<const float4*>(&(is2 ? x2a0 : x1a0)[src * 512 + col - 300]);
    else if (col < 1324)  v = *reinterpret_cast<const float4*>(&(is2 ? x2a1 : x1a1)[src * 512 + col - 812]);
    uint2 H, L;
    bsplit2pack(v.x, v.y, H.x, L.x);
    bsplit2pack(v.z, v.w, H.y, L.y);
    *reinterpret_cast<uint2*>(&g_xatt_hi[(size_t)idx * 4]) = H;
    *reinterpret_cast<uint2*>(&g_xatt_lo[(size_t)idx * 4]) = L;
}

__global__ void k_build_U(const float* __restrict__ U0, const float* __restrict__ U1,
                          const float* __restrict__ U2) {
    int idx = blockIdx.x * blockDim.x + threadIdx.x;
    const int total4 = ND3 * (ATTP / 4);
    if (idx >= total4) return;
    int row = idx / (ATTP / 4);
    int col = (idx - row * (ATTP / 4)) * 4;
    int head = row >> 8, j = row & 255;
    float4 v = make_float4(0.f, 0.f, 0.f, 0.f);
    if (j < 250 && col < 1324) {
        const float* U = (head == 0) ? U0 : (head == 1 ? U1 : U2);
        v = *reinterpret_cast<const float4*>(&U[j * 1324 + col]);
    }
    uint2 H, L;
    bsplit2pack(v.x, v.y, H.x, L.x);
    bsplit2pack(v.z, v.w, H.y, L.y);
    *reinterpret_cast<uint2*>(&g_U_hi[(size_t)idx * 4]) = H;
    *reinterpret_cast<uint2*>(&g_U_lo[(size_t)idx * 4]) = L;
}

__global__ void k_build_dvec(const float* __restrict__ d0, const float* __restrict__ d1,
                             const float* __restrict__ d2) {
    int i = blockIdx.x * blockDim.x + threadIdx.x;
    if (i >= ND3) return;
    int head = i >> 8, j = i & 255;
    const float* d = (head == 0) ? d0 : (head == 1 ? d1 : d2);
    g_dvec[i] = (j < 250) ? d[j] : 0.f;
}

__global__ void k_build_W(const float* __restrict__ Wf, const float* __restrict__ Wb) {
    int idx = blockIdx.x * blockDim.x + threadIdx.x;
    const int total4 = NGATE * (RNNIN / 4);
    if (idx >= total4) return;
    int row = idx / (RNNIN / 4);
    int col = (idx - row * (RNNIN / 4)) * 4;
    float4 v = *reinterpret_cast<const float4*>(
        &((row >= 1024) ? Wb : Wf)[(row & 1023) * RNNIN + col]);
    uint2 H, L;
    bsplit2pack(v.x, v.y, H.x, L.x);
    bsplit2pack(v.z, v.w, H.y, L.y);
    *reinterpret_cast<uint2*>(&g_W_hi[(size_t)idx * 4]) = H;
    *reinterpret_cast<uint2*>(&g_W_lo[(size_t)idx * 4]) = L;
}

__global__ void k_build_bias(const float* __restrict__ bif, const float* __restrict__ bhf,
                             const float* __restrict__ bib, const float* __restrict__ bhb) {
    int i = blockIdx.x * blockDim.x + threadIdx.x;
    if (i >= NGATE) return;
    int j = i & 1023;
    g_bias[i] = (i >= 1024) ? (bib[j] + bhb[j]) : (bif[j] + bhf[j]);
}

__global__ void k_build_x1head(const float* __restrict__ x1a0, const float* __restrict__ x1a1) {
    int idx = blockIdx.x * blockDim.x + threadIdx.x;
    const int total4 = NB * LL * 256;
    if (idx >= total4) return;
    int row = idx >> 8;
    int col = (idx & 255) * 4;
    float4 v = (col < 512)
        ? *reinterpret_cast<const float4*>(&x1a0[row * 512 + col])
        : *reinterpret_cast<const float4*>(&x1a1[row * 512 + col - 512]);
    uint2 H, L;
    bsplit2pack(v.x, v.y, H.x, L.x);
    bsplit2pack(v.z, v.w, H.y, L.y);
    size_t o = (size_t)row * RNNIN + col;
    *reinterpret_cast<uint2*>(&g_x1_hi[o]) = H;
    *reinterpret_cast<uint2*>(&g_x1_lo[o]) = L;
}

__global__ void k_zero_h() {
    int i = blockIdx.x * blockDim.x + threadIdx.x;
    if (i < 2 * 2 * NB * HID) ((float*)g_h)[i] = 0.f;
}

// x3t[z][h][m] = x3[b][m][h], z = head*32+b; bf162-packed writes.
__global__ void k_x3t(const float* __restrict__ x0, const float* __restrict__ x1,
                      const float* __restrict__ x2) {
    __shared__ float t[64][33];
    int z = blockIdx.z;
    int head = z >> 5, bb = z & 31;
    const float* in = ((head == 0) ? x0 : (head == 1) ? x1 : x2) + (size_t)bb * 262144;
    bf16* oh = g_x3t_hi + (size_t)z * 262144;
    bf16* ol = g_x3t_lo + (size_t)z * 262144;
    int m0 = blockIdx.y * 64, h0 = blockIdx.x * 32;
    int tx = threadIdx.x, ty = threadIdx.y;
    #pragma unroll
    for (int i = 0; i < 8; i++)
        t[ty + 8 * i][tx] = in[(size_t)(m0 + ty + 8 * i) * 512 + h0 + tx];
    __syncthreads();
    #pragma unroll
    for (int i = 0; i < 4; i++) {
        int hr = ty + 8 * i;
        float a = t[2 * tx][hr], b = t[2 * tx + 1][hr];
        uint32_t H, L;
        bsplit2pack(a, b, H, L);
        size_t o = (size_t)(h0 + hr) * 512 + m0 + 2 * tx;
        *reinterpret_cast<uint32_t*>(oh + o) = H;
        *reinterpret_cast<uint32_t*>(ol + o) = L;
    }
}

// ----------------------------- PTX helpers ---------------------------------
__device__ __forceinline__ uint32_t smem_u32(const void* p) {
    uint32_t a;
    asm("{ .reg .u64 t; cvta.to.shared.u64 t, %1; cvt.u32.u64 %0, t; }" : "=r"(a) : "l"(p));
    return a;
}

__device__ __forceinline__ void cp16(uint32_t dst, const void* src) {
    asm volatile("cp.async.cg.shared.global [%0], [%1], 16;" :: "r"(dst), "l"(src) : "memory");
}

__device__ __forceinline__ void ldsm4(uint32_t* r, uint32_t addr) {
    asm volatile("ldmatrix.sync.aligned.m8n8.x4.shared.b16 {%0,%1,%2,%3}, [%4];"
                 : "=r"(r[0]), "=r"(r[1]), "=r"(r[2]), "=r"(r[3]) : "r"(addr));
}

__device__ __forceinline__ void mma16816(float* c, const uint32_t* a, const uint32_t* b) {
    asm volatile(
        "mma.sync.aligned.m16n8k16.row.col.f32.bf16.bf16.f32 "
        "{%0,%1,%2,%3}, {%4,%5,%6,%7}, {%8,%9}, {%0,%1,%2,%3};"
        : "+f"(c[0]), "+f"(c[1]), "+f"(c[2]), "+f"(c[3])
        : "r"(a[0]), "r"(a[1]), "r"(a[2]), "r"(a[3]), "r"(b[0]), "r"(b[1]));
}

// ------------------------------- MMA GEMM ----------------------------------
// C[128x128] = A[128,K] @ B[128,K]^T, bf16 split (AhBh+AhBl+AlBh).
// k32 stages (4 arrays x 8KB = 32KB/stage), 3-stage cp.async pipeline,
// 97KB dsmem -> 2 CTAs/SM (4 warps/SMSP). 64B rows, u ^ ((row>>1)&3) swizzle.
#define STAGE_BYTES 32768
#define DSMEM_BYTES (3 * STAGE_BYTES + 1024)

template <int MODE>
__global__ __launch_bounds__(256, 2) void mma_k(const unsigned char* __restrict__ mask8) {
    extern __shared__ char dsm_raw[];
    const int tid = threadIdx.x;
    const int lane = tid & 31, wid = tid >> 5;
    const int wm = wid >> 2, wn = wid & 3;           // warp grid 2(m) x 4(n)
    const int col0 = blockIdx.x * 128, row0 = blockIdx.y * 128, z = blockIdx.z;

    const bf16 *pAh, *pAl, *pBh, *pBl;
    int ld, S, head = 0, bb = 0;
    if constexpr (MODE == 0) {
        ld = ATTP; S = ATTP / 32;
        pAh = g_xatt_hi + (size_t)row0 * ld; pAl = g_xatt_lo + (size_t)row0 * ld;
        pBh = g_U_hi   + (size_t)col0 * ld; pBl = g_U_lo   + (size_t)col0 * ld;
    } else if constexpr (MODE == 1) {
        head = z >> 5; bb = z & 31; ld = ND3; S = 8;
        size_t a0 = (size_t)(bb * 512 + row0) * ND3 + head * 256;
        size_t b0 = (size_t)(16384 + bb * 512 + col0) * ND3 + head * 256;
        pAh = g_r_hi + a0; pAl = g_r_lo + a0;
        pBh = g_r_hi + b0; pBl = g_r_lo + b0;
    } else if constexpr (MODE == 2) {
        head = z >> 5; bb = z & 31; ld = 512; S = 16;
        size_t a0 = (size_t)z * 262144 + (size_t)row0 * 512;
        size_t b0 = (size_t)z * 262144 + (size_t)col0 * 512;
        pAh = g_al_hi + a0; pAl = g_al_lo + a0;
        pBh = g_x3t_hi + b0; pBl = g_x3t_lo + b0;
    } else {
        ld = RNNIN; S = RNNIN / 32;
        pAh = g_x1_hi + (size_t)row0 * ld; pAl = g_x1_lo + (size_t)row0 * ld;
        pBh = g_W_hi + (size_t)col0 * ld;  pBl = g_W_lo + (size_t)col0 * ld;
    }

    const uint32_t sb = (smem_u32(dsm_raw) + 1023u) & ~1023u;

    float acc[4][4][4];
    #pragma unroll
    for (int i = 0; i < 4; i++)
        #pragma unroll
        for (int j = 0; j < 4; j++)
            #pragma unroll
            for (int q = 0; q < 4; q++) acc[i][j][q] = 0.f;

    const int a_row16 = lane & 15, a_half = lane >> 4;
    const int b_nrow  = (lane & 7) + ((lane >> 4) & 1) * 8;
    const int b_half  = (lane >> 3) & 1;

    // stage loader: 4 arrays x 8KB, 64B rows, 16B-chunk swizzle u^((row>>1)&3)
    #define ISSUE_STAGE(s)                                                         \
        do {                                                                       \
            const uint32_t sbase_ = sb + ((s) % 3) * STAGE_BYTES;                  \
            _Pragma("unroll")                                                      \
            for (int i = 0; i < 8; i++) {                                          \
                const int arr = i >> 1;                                            \
                const int idx = ((i & 1) << 8) + tid;                              \
                const int row = idx >> 2, u = idx & 3;                             \
                const bf16* p = (arr == 0) ? pAh : (arr == 1) ? pAl                \
                               : (arr == 2) ? pBh : pBl;                           \
                cp16(sbase_ + (arr << 13) + (row << 6) +                           \
                         (((u ^ ((row >> 1) & 3)) << 4)),                          \
                     p + (size_t)row * ld + (size_t)(s) * 32 + u * 8);             \
            }                                                                      \
            asm volatile("cp.async.commit_group;" ::: "memory");                   \
        } while (0)

    ISSUE_STAGE(0);
    ISSUE_STAGE(1);
    for (int s = 0; s < S; s++) {
        if (s + 2 <= S) asm volatile("cp.async.wait_group 1;" ::: "memory");
        else            asm volatile("cp.async.wait_group 0;" ::: "memory");
        __syncthreads();
        if (s + 2 < S) ISSUE_STAGE(s + 2);

        const uint32_t sbase = sb + (s % 3) * STAGE_BYTES;
        const uint32_t sAh = sbase, sAl = sbase + 8192;
        const uint32_t sBh = sbase + 16384, sBl = sbase + 24576;

        #pragma unroll
        for (int kk = 0; kk < 2; kk++) {
            uint32_t ah[4][4], al[4][4], bh[2][4], bl[2][4];
            #pragma unroll
            for (int np = 0; np < 2; np++) {
                const int nr = wn * 32 + np * 16 + b_nrow;
                const int u = kk * 2 + b_half;
                const uint32_t off = (nr << 6) + ((u ^ ((nr >> 1) & 3)) << 4);
                ldsm4(bh[np], sBh + off);
                ldsm4(bl[np], sBl + off);
            }
            #pragma unroll
            for (int mt = 0; mt < 4; mt++) {
                const int row = wm * 64 + mt * 16 + a_row16;
                const int u = kk * 2 + a_half;
                const uint32_t off = (row << 6) + ((u ^ ((row >> 1) & 3)) << 4);
                ldsm4(ah[mt], sAh + off);
                ldsm4(al[mt], sAl + off);
            }
            #pragma unroll
            for (int mt = 0; mt < 4; mt++)
                #pragma unroll
                for (int nt = 0; nt < 4; nt++) {
                    const uint32_t* B2h = &bh[nt >> 1][(nt & 1) * 2];
                    const uint32_t* B2l = &bl[nt >> 1][(nt & 1) * 2];
                    mma16816(acc[mt][nt], ah[mt], B2h);
                    mma16816(acc[mt][nt], ah[mt], B2l);
                    mma16816(acc[mt][nt], al[mt], B2h);
                }
        }
    }
    #undef ISSUE_STAGE

    // ----------------------------- epilogue --------------------------------
    #pragma unroll
    for (int mt = 0; mt < 4; mt++) {
        #pragma unroll
        for (int nt = 0; nt < 4; nt++) {
            const int mA = row0 + wm * 64 + mt * 16 + (lane >> 2);
            const int mB = mA + 8;
            const int nloc = col0 + wn * 32 + nt * 8 + (lane & 3) * 2;
            const float* c = acc[mt][nt];
            if constexpr (MODE == 0) {
                const bool isx2 = (row0 >= 16384);
                const float dv0 = isx2 ? g_dvec[nloc] : 1.f;
                const float dv1 = isx2 ? g_dvec[nloc + 1] : 1.f;
                #pragma unroll
                for (int half = 0; half < 2; half++) {
                    const int m = half ? mB : mA;
                    float v0 = fmaxf(c[half * 2 + 0], 0.f) * dv0;
                    float v1 = fmaxf(c[half * 2 + 1], 0.f) * dv1;
                    uint32_t H, L;
                    bsplit2pack(v0, v1, H, L);
                    *reinterpret_cast<uint32_t*>(g_r_hi + (size_t)m * ND3 + nloc) = H;
                    *reinterpret_cast<uint32_t*>(g_r_lo + (size_t)m * ND3 + nloc) = L;
                }
            } else if constexpr (MODE == 1) {
                const bool m0k = mask8[(size_t)bb * 512 + nloc] != 0;
                const bool m1k = mask8[(size_t)bb * 512 + nloc + 1] != 0;
                #pragma unroll
                for (int half = 0; half < 2; half++) {
                    const int m = half ? mB : mA;
                    float2 v;
                    v.x = m0k ? -1e30f : c[half * 2 + 0];
                    v.y = m1k ? -1e30f : c[half * 2 + 1];
                    *reinterpret_cast<float2*>(g_scores + (size_t)z * 262144 +
                                               (size_t)m * 512 + nloc) = v;
                }
            } else if constexpr (MODE == 2) {
                #pragma unroll
                for (int half = 0; half < 2; half++) {
                    const int m = half ? mB : mA;
                    uint32_t H, L;
                    bsplit2pack(c[half * 2 + 0], c[half * 2 + 1], H, L);
                    size_t o = (size_t)(bb * 512 + m) * RNNIN + 1024 + head * 512 + nloc;
                    *reinterpret_cast<uint32_t*>(g_x1_hi + o) = H;
                    *reinterpret_cast<uint32_t*>(g_x1_lo + o) = L;
                }
            } else {
                const float b0 = g_bias[nloc], b1 = g_bias[nloc + 1];
                #pragma unroll
                for (int half = 0; half < 2; half++) {
                    const int m = half ? mB : mA;
                    float2 v;
                    v.x = c[half * 2 + 0] + b0;
                    v.y = c[half * 2 + 1] + b1;
                    *reinterpret_cast<float2*>(g_gates + (size_t)m * NGATE + nloc) = v;
                }
            }
        }
    }
}

// ------------------------------ softmax ------------------------------------
__global__ void softmax_k() {
    const float* p = g_scores + (size_t)blockIdx.x * 512;
    bf16* oh = g_al_hi + (size_t)blockIdx.x * 512;
    bf16* ol = g_al_lo + (size_t)blockIdx.x * 512;
    const int t = threadIdx.x;  // 128 threads * 4 = 512
    float4 v = reinterpret_cast<const float4*>(p)[t];
    float mx = fmaxf(fmaxf(v.x, v.y), fmaxf(v.z, v.w));
    #pragma unroll
    for (int o = 16; o; o >>= 1) mx = fmaxf(mx, __shfl_xor_sync(0xffffffffu, mx, o));
    __shared__ float red[4], red2[4];
    if ((t & 31) == 0) red[t >> 5] = mx;
    __syncthreads();
    mx = fmaxf(fmaxf(red[0], red[1]), fmaxf(red[2], red[3]));
    v.x = __expf(v.x - mx); v.y = __expf(v.y - mx);
    v.z = __expf(v.z - mx); v.w = __expf(v.w - mx);
    float s = v.x + v.y + v.z + v.w;
    #pragma unroll
    for (int o = 16; o; o >>= 1) s += __shfl_xor_sync(0xffffffffu, s, o);
    if ((t & 31) == 0) red2[t >> 5] = s;
    __syncthreads();
    s = red2[0] + red2[1] + red2[2] + red2[3];
    float inv = 1.f / s;
    v.x *= inv; v.y *= inv; v.z *= inv; v.w *= inv;
    uint32_t H0, L0, H1, L1;
    bsplit2pack(v.x, v.y, H0, L0);
    bsplit2pack(v.z, v.w, H1, L1);
    reinterpret_cast<uint32_t*>(oh)[t * 2]     = H0;
    reinterpret_cast<uint32_t*>(oh)[t * 2 + 1] = H1;
    reinterpret_cast<uint32_t*>(ol)[t * 2]     = L0;
    reinterpret_cast<uint32_t*>(ol)[t * 2 + 1] = L1;
}

// ------------------------------- LSTM --------------------------------------
// smem layout (dynamic): Wsh[16][256] | h_s[32][260] | z_s[16][32]
#define LSTM_SMEM ((16 * 256 + 32 * 260 + 16 * 32) * 4)

__device__ __forceinline__ float sigmf_(float x) { return 1.f / (1.f + __expf(-x)); }
__device__ __forceinline__ float tanhf_(float x) { return 2.f / (1.f + __expf(-2.f * x)) - 1.f; }

__global__ __launch_bounds__(256, 1) void lstm_k(float* __restrict__ out,
                                                 const float* __restrict__ Whh_f,
                                                 const float* __restrict__ Whh_b) {
    extern __shared__ float lsm[];
    float (*Wsh)[256] = (float (*)[256])lsm;
    float (*h_s)[260] = (float (*)[260])(lsm + 16 * 256);
    float (*z_s)[32]  = (float (*)[32])(lsm + 16 * 256 + 32 * 260);
    __shared__ unsigned base_s;

    const int tid = threadIdx.x;
    const int blk = blockIdx.x;
    const int dir = blk >> 6;
    const int u0  = (blk & 63) * 4;

    const float* Whh = dir ? Whh_b : Whh_f;
    {
        int zl = tid >> 4;
        int gate = zl >> 2, j = zl & 3;
        int grow = gate * 256 + u0 + j;
        int c4 = tid & 15;
        #pragma unroll
        for (int i = 0; i < 4; i++) {
            int k4 = c4 + 16 * i;
            reinterpret_cast<float4*>(&Wsh[zl][0])[k4] =
                reinterpret_cast<const float4*>(Whh + (size_t)grow * 256)[k4];
        }
    }
    if (tid == 0) base_s = *((volatile unsigned*)&g_release);
    __syncthreads();
    const unsigned base = base_s;

    float c_reg = 0.f;
    int cur = 0;
    const int b  = tid & 31;
    const int zg = tid >> 5;
    const int zl0 = zg * 2, zl1 = zg * 2 + 1;
    const int g0 = zl0 >> 2, j0 = zl0 & 3;
    const int g1 = zl1 >> 2, j1 = zl1 & 3;
    const int col0 = dir * 1024 + g0 * 256 + u0 + j0;
    const int col1 = dir * 1024 + g1 * 256 + u0 + j1;

    int tt0 = dir ? 511 : 0;
    float gate0 = g_gates[(size_t)(b * 512 + tt0) * NGATE + col0];
    float gate1 = g_gates[(size_t)(b * 512 + tt0) * NGATE + col1];

    for (int s = 0; s < 512; s++) {
        const int tt = dir ? (511 - s) : s;

        #pragma unroll
        for (int i = 0; i < 8; i++) {
            int f4 = tid + 256 * i;
            int bb2 = f4 >> 6, k4 = f4 & 63;
            float4 hv = reinterpret_cast<const float4*>(&g_h[cur][dir][bb2][0])[k4];
            *reinterpret_cast<float4*>(&h_s[bb2][k4 * 4]) = hv;
        }
        __syncthreads();

        float acc0 = gate0, acc1 = gate1;
        #pragma unroll 8
        for (int k = 0; k < 256; k += 4) {
            float4 h4 = *reinterpret_cast<const float4*>(&h_s[b][k]);
            float4 w0 = *reinterpret_cast<const float4*>(&Wsh[zl0][k]);
            float4 w1 = *reinterpret_cast<const float4*>(&Wsh[zl1][k]);
            acc0 = fmaf(h4.x, w0.x, acc0); acc0 = fmaf(h4.y, w0.y, acc0);
            acc0 = fmaf(h4.z, w0.z, acc0); acc0 = fmaf(h4.w, w0.w, acc0);
            acc1 = fmaf(h4.x, w1.x, acc1); acc1 = fmaf(h4.y, w1.y, acc1);
            acc1 = fmaf(h4.z, w1.z, acc1); acc1 = fmaf(h4.w, w1.w, acc1);
        }
        z_s[zl0][b] = acc0;
        z_s[zl1][b] = acc1;
        __syncthreads();

        float hval = 0.f;
        int bb2 = tid & 31, j = tid >> 5;
        if (tid < 128) {
            float zi = z_s[0 * 4 + j][bb2];
            float zf = z_s[1 * 4 + j][bb2];
            float zgv = z_s[2 * 4 + j][bb2];
            float zo = z_s[3 * 4 + j][bb2];
            c_reg = sigmf_(zf) * c_reg + sigmf_(zi) * tanhf_(zgv);
            hval = sigmf_(zo) * tanhf_(c_reg);
            g_h[cur ^ 1][dir][bb2][u0 + j] = hval;
        }
        __syncthreads();

        const unsigned target = base + (unsigned)s + 1u;
        bool is_setter = false;
        if (tid == 0) {
            __threadfence();
            unsigned old = atomicAdd(&g_count, 1u);
            is_setter = (old == target * LSTM_NB - 1u);
        }

        // overlapped with barrier propagation
        if (tid < 128)
            out[(size_t)(bb2 * 512 + tt) * 512 + dir * 256 + u0 + j] = hval;
        if (s + 1 < 512) {
            const int ttn = dir ? (511 - (s + 1)) : (s + 1);
            gate0 = g_gates[(size_t)(b * 512 + ttn) * NGATE + col0];
            gate1 = g_gates[(size_t)(b * 512 + ttn) * NGATE + col1];
        }

        if (tid == 0) {
            if (is_setter) {
                __threadfence();
                *((volatile unsigned*)&g_release) = target;
            } else {
                while ((int)(*((volatile unsigned*)&g_release) - target) < 0) __nanosleep(32);
            }
            __threadfence();
        }
        __syncthreads();
        cur ^= 1;
    }
}

// ------------------------------ launch -------------------------------------
static inline int cdiv(int a, int b) { return (a + b - 1) / b; }

extern "C" void kernel_launch(void* const* d_in, const int* in_sizes, int n_in,
                              void* d_out, int out_size) {
    (void)in_sizes; (void)n_in; (void)out_size;
    const float* x1w  = (const float*)d_in[0];
    const float* x1a0 = (const float*)d_in[1];
    const float* x1a1 = (const float*)d_in[2];
    const float* x2w  = (const float*)d_in[3];
    const float* x2a0 = (const float*)d_in[4];
    const float* x2a1 = (const float*)d_in[5];
    const float* x2a2 = (const float*)d_in[6];
    const unsigned char* x2mask = (const unsigned char*)d_in[8];
    const float* U0 = (const float*)d_in[9];
    const float* d0 = (const float*)d_in[10];
    const float* U1 = (const float*)d_in[11];
    const float* d1 = (const float*)d_in[12];
    const float* U2 = (const float*)d_in[13];
    const float* d2 = (const float*)d_in[14];
    const float* Wihf = (const float*)d_in[15];
    const float* Whhf = (const float*)d_in[16];
    const float* bihf = (const float*)d_in[17];
    const float* bhhf = (const float*)d_in[18];
    const float* Wihb = (const float*)d_in[19];
    const float* Whhb = (const float*)d_in[20];
    const float* bihb = (const float*)d_in[21];
    const float* bhhb = (const float*)d_in[22];
    float* out = (float*)d_out;

    cudaFuncSetAttribute(mma_k<0>, cudaFuncAttributeMaxDynamicSharedMemorySize, DSMEM_BYTES);
    cudaFuncSetAttribute(mma_k<1>, cudaFuncAttributeMaxDynamicSharedMemorySize, DSMEM_BYTES);
    cudaFuncSetAttribute(mma_k<2>, cudaFuncAttributeMaxDynamicSharedMemorySize, DSMEM_BYTES);
    cudaFuncSetAttribute(mma_k<3>, cudaFuncAttributeMaxDynamicSharedMemorySize, DSMEM_BYTES);
    cudaFuncSetAttribute(lstm_k, cudaFuncAttributeMaxDynamicSharedMemorySize, LSTM_SMEM);

    // launch order tuned so ncu (-s 5 => our launch index 3) captures mma_k<0>
    k_build_xatt<<<cdiv(2 * NB * LL * (ATTP / 4), 256), 256>>>(x1w, x1a0, x1a1, x2w, x2a0, x2a1);
    k_build_U<<<cdiv(ND3 * (ATTP / 4), 256), 256>>>(U0, U1, U2);
    k_build_dvec<<<cdiv(ND3, 256), 256>>>(d0, d1, d2);
    // r = relu(xatt @ U^T): M=32768, N=768, K=1344
    mma_k<0><<<dim3(ND3 / 128, 256, 1), 256, DSMEM_BYTES>>>(nullptr);

    k_build_W<<<cdiv(NGATE * (RNNIN / 4), 256), 256>>>(Wihf, Wihb);
    k_build_bias<<<cdiv(NGATE, 256), 256>>>(bihf, bhhf, bihb, bhhb);
    k_build_x1head<<<cdiv(NB * LL * 256, 256), 256>>>(x1a0, x1a1);
    k_zero_h<<<cdiv(2 * 2 * NB * HID, 256), 256>>>();
    k_x3t<<<dim3(16, 8, 96), dim3(32, 8)>>>(x2a0, x2a1, x2a2);

    // scores per (head,b): 512x512x256
    mma_k<1><<<dim3(4, 4, 96), 256, DSMEM_BYTES>>>(x2mask);
    softmax_k<<<3 * NB * LL, 128>>>();
    // attn = alpha @ x3t^T: 512x512x512 per (head,b)
    mma_k<2><<<dim3(4, 4, 96), 256, DSMEM_BYTES>>>(nullptr);
    // gates = x1 @ W^T + bias: M=16384, N=2048, K=2560
    mma_k<3><<<dim3(NGATE / 128, 128, 1), 256, DSMEM_BYTES>>>(nullptr);
    // BiLSTM recurrence
    lstm_k<<<LSTM_NB, 256, LSTM_SMEM>>>(out, Whhf, Whhb);
}

// round 15
// speedup vs baseline: 1.2348x; 1.2348x over previous
#include <cuda_runtime.h>
#include <cuda_bf16.h>
#include <cstdint>

// ---------------------------------------------------------------------------
// DeepAttention: 3x multiplicative attention + BiLSTM.
// GEMMs via mma.sync HMMA bf16 (hi/lo split, 3-term), 3-stage cp.async pipe
// (round-4 best config). LSTM: recurrent z-GEMM on HMMA (bf16 split, 8-warp
// k-split + smem reduction), atomicAdd+release grid barrier.
// ---------------------------------------------------------------------------

#define AL16 __align__(16)

#define NB 32
#define LL 512
#define ATTP 1344      // 1324 padded to 21*64
#define ND3 768        // 3 heads * 256
#define RNNIN 2560
#define NGATE 2048
#define HID 256
#define LSTM_NB 128

typedef __nv_bfloat16 bf16;

// ------------------------------- scratch -----------------------------------
__device__ AL16 bf16  g_xatt_hi[2 * NB * LL * ATTP];
__device__ AL16 bf16  g_xatt_lo[2 * NB * LL * ATTP];
__device__ AL16 bf16  g_U_hi[ND3 * ATTP];
__device__ AL16 bf16  g_U_lo[ND3 * ATTP];
__device__ AL16 float g_dvec[ND3];
__device__ AL16 bf16  g_r_hi[2 * NB * LL * ND3];
__device__ AL16 bf16  g_r_lo[2 * NB * LL * ND3];
__device__ AL16 float g_scores[3 * NB * LL * LL];
__device__ AL16 bf16  g_al_hi[3 * NB * LL * LL];
__device__ AL16 bf16  g_al_lo[3 * NB * LL * LL];
__device__ AL16 bf16  g_x3t_hi[3 * NB * LL * LL];
__device__ AL16 bf16  g_x3t_lo[3 * NB * LL * LL];
__device__ AL16 bf16  g_x1_hi[NB * LL * RNNIN];
__device__ AL16 bf16  g_x1_lo[NB * LL * RNNIN];
__device__ AL16 bf16  g_W_hi[NGATE * RNNIN];
__device__ AL16 bf16  g_W_lo[NGATE * RNNIN];
__device__ AL16 float g_bias[NGATE];
__device__ AL16 float g_gates[NB * LL * NGATE];
// LSTM h state as bf16 hi/lo: [parity][dir][batch][unit]
__device__ AL16 bf16  g_hh[2][2][NB][HID];
__device__ AL16 bf16  g_hl[2][2][NB][HID];
__device__ unsigned g_count;      // grid barrier (monotonic)
__device__ unsigned g_release;

__device__ __forceinline__ void bsplit(float v, bf16& h, bf16& l) {
    h = __float2bfloat16(v);
    l = __float2bfloat16(v - __bfloat162float(h));
}

__device__ __forceinline__ void bsplit2pack(float a, float b, uint32_t& hi, uint32_t& lo) {
    bf16 ha, la, hb, lb;
    bsplit(a, ha, la); bsplit(b, hb, lb);
    __nv_bfloat162 H; H.x = ha; H.y = hb;
    __nv_bfloat162 L; L.x = la; L.y = lb;
    hi = *reinterpret_cast<uint32_t*>(&H);
    lo = *reinterpret_cast<uint32_t*>(&L);
}

// ----------------------------- build kernels (vectorized) ------------------
__global__ void k_build_xatt(const float* __restrict__ x1w, const float* __restrict__ x1a0,
                             const float* __restrict__ x1a1, const float* __restrict__ x2w,
                             const float* __restrict__ x2a0, const float* __restrict__ x2a1) {
    int idx = blockIdx.x * blockDim.x + threadIdx.x;
    const int total4 = 2 * NB * LL * (ATTP / 4);
    if (idx >= total4) return;
    int row = idx / (ATTP / 4);
    int col = (idx - row * (ATTP / 4)) * 4;
    int src = row & 16383;
    bool is2 = row >= 16384;
    float4 v = make_float4(0.f, 0.f, 0.f, 0.f);
    if (col < 300)        v = *reinterpret_cast<const float4*>(&(is2 ? x2w  : x1w )[src * 300 + col]);
    else if (col < 812)   v = *reinterpret_cast<const float4*>(&(is2 ? x2a0 : x1a0)[src * 512 + col - 300]);
    else if (col < 1324)  v = *reinterpret_cast<const float4*>(&(is2 ? x2a1 : x1a1)[src * 512 + col - 812]);
    uint2 H, L;
    bsplit2pack(v.x, v.y, H.x, L.x);
    bsplit2pack(v.z, v.w, H.y, L.y);
    *reinterpret_cast<uint2*>(&g_xatt_hi[(size_t)idx * 4]) = H;
    *reinterpret_cast<uint2*>(&g_xatt_lo[(size_t)idx * 4]) = L;
}

__global__ void k_build_U(const float* __restrict__ U0, const float* __restrict__ U1,
                          const float* __restrict__ U2) {
    int idx = blockIdx.x * blockDim.x + threadIdx.x;
    const int total4 = ND3 * (ATTP / 4);
    if (idx >= total4) return;
    int row = idx / (ATTP / 4);
    int col = (idx - row * (ATTP / 4)) * 4;
    int head = row >> 8, j = row & 255;
    float4 v = make_float4(0.f, 0.f, 0.f, 0.f);
    if (j < 250 && col < 1324) {
        const float* U = (head == 0) ? U0 : (head == 1 ? U1 : U2);
        v = *reinterpret_cast<const float4*>(&U[j * 1324 + col]);
    }
    uint2 H, L;
    bsplit2pack(v.x, v.y, H.x, L.x);
    bsplit2pack(v.z, v.w, H.y, L.y);
    *reinterpret_cast<uint2*>(&g_U_hi[(size_t)idx * 4]) = H;
    *reinterpret_cast<uint2*>(&g_U_lo[(size_t)idx * 4]) = L;
}

__global__ void k_build_dvec(const float* __restrict__ d0, const float* __restrict__ d1,
                             const float* __restrict__ d2) {
    int i = blockIdx.x * blockDim.x + threadIdx.x;
    if (i >= ND3) return;
    int head = i >> 8, j = i & 255;
    const float* d = (head == 0) ? d0 : (head == 1 ? d1 : d2);
    g_dvec[i] = (j < 250) ? d[j] : 0.f;
}

__global__ void k_build_W(const float* __restrict__ Wf, const float* __restrict__ Wb) {
    int idx = blockIdx.x * blockDim.x + threadIdx.x;
    const int total4 = NGATE * (RNNIN / 4);
    if (idx >= total4) return;
    int row = idx / (RNNIN / 4);
    int col = (idx - row * (RNNIN / 4)) * 4;
    float4 v = *reinterpret_cast<const float4*>(
        &((row >= 1024) ? Wb : Wf)[(row & 1023) * RNNIN + col]);
    uint2 H, L;
    bsplit2pack(v.x, v.y, H.x, L.x);
    bsplit2pack(v.z, v.w, H.y, L.y);
    *reinterpret_cast<uint2*>(&g_W_hi[(size_t)idx * 4]) = H;
    *reinterpret_cast<uint2*>(&g_W_lo[(size_t)idx * 4]) = L;
}

__global__ void k_build_bias(const float* __restrict__ bif, const float* __restrict__ bhf,
                             const float* __restrict__ bib, const float* __restrict__ bhb) {
    int i = blockIdx.x * blockDim.x + threadIdx.x;
    if (i >= NGATE) return;
    int j = i & 1023;
    g_bias[i] = (i >= 1024) ? (bib[j] + bhb[j]) : (bif[j] + bhf[j]);
}

__global__ void k_build_x1head(const float* __restrict__ x1a0, const float* __restrict__ x1a1) {
    int idx = blockIdx.x * blockDim.x + threadIdx.x;
    const int total4 = NB * LL * 256;
    if (idx >= total4) return;
    int row = idx >> 8;
    int col = (idx & 255) * 4;
    float4 v = (col < 512)
        ? *reinterpret_cast<const float4*>(&x1a0[row * 512 + col])
        : *reinterpret_cast<const float4*>(&x1a1[row * 512 + col - 512]);
    uint2 H, L;
    bsplit2pack(v.x, v.y, H.x, L.x);
    bsplit2pack(v.z, v.w, H.y, L.y);
    size_t o = (size_t)row * RNNIN + col;
    *reinterpret_cast<uint2*>(&g_x1_hi[o]) = H;
    *reinterpret_cast<uint2*>(&g_x1_lo[o]) = L;
}

__global__ void k_zero_h() {
    int i = blockIdx.x * blockDim.x + threadIdx.x;
    const int n = 2 * 2 * NB * HID;
    if (i < n) {
        ((bf16*)g_hh)[i] = __float2bfloat16(0.f);
        ((bf16*)g_hl)[i] = __float2bfloat16(0.f);
    }
}

// x3t[z][h][m] = x3[b][m][h], z = head*32+b; bf162-packed writes.
__global__ void k_x3t(const float* __restrict__ x0, const float* __restrict__ x1,
                      const float* __restrict__ x2) {
    __shared__ float t[64][33];
    int z = blockIdx.z;
    int head = z >> 5, bb = z & 31;
    const float* in = ((head == 0) ? x0 : (head == 1) ? x1 : x2) + (size_t)bb * 262144;
    bf16* oh = g_x3t_hi + (size_t)z * 262144;
    bf16* ol = g_x3t_lo + (size_t)z * 262144;
    int m0 = blockIdx.y * 64, h0 = blockIdx.x * 32;
    int tx = threadIdx.x, ty = threadIdx.y;
    #pragma unroll
    for (int i = 0; i < 8; i++)
        t[ty + 8 * i][tx] = in[(size_t)(m0 + ty + 8 * i) * 512 + h0 + tx];
    __syncthreads();
    #pragma unroll
    for (int i = 0; i < 4; i++) {
        int hr = ty + 8 * i;
        float a = t[2 * tx][hr], b = t[2 * tx + 1][hr];
        uint32_t H, L;
        bsplit2pack(a, b, H, L);
        size_t o = (size_t)(h0 + hr) * 512 + m0 + 2 * tx;
        *reinterpret_cast<uint32_t*>(oh + o) = H;
        *reinterpret_cast<uint32_t*>(ol + o) = L;
    }
}

// ----------------------------- PTX helpers ---------------------------------
__device__ __forceinline__ uint32_t smem_u32(const void* p) {
    uint32_t a;
    asm("{ .reg .u64 t; cvta.to.shared.u64 t, %1; cvt.u32.u64 %0, t; }" : "=r"(a) : "l"(p));
    return a;
}

__device__ __forceinline__ void cp16(uint32_t dst, const void* src) {
    asm volatile("cp.async.cg.shared.global [%0], [%1], 16;" :: "r"(dst), "l"(src) : "memory");
}

__device__ __forceinline__ void ldsm4(uint32_t* r, uint32_t addr) {
    asm volatile("ldmatrix.sync.aligned.m8n8.x4.shared.b16 {%0,%1,%2,%3}, [%4];"
                 : "=r"(r[0]), "=r"(r[1]), "=r"(r[2]), "=r"(r[3]) : "r"(addr));
}

__device__ __forceinline__ void mma16816(float* c, const uint32_t* a, const uint32_t* b) {
    asm volatile(
        "mma.sync.aligned.m16n8k16.row.col.f32.bf16.bf16.f32 "
        "{%0,%1,%2,%3}, {%4,%5,%6,%7}, {%8,%9}, {%0,%1,%2,%3};"
        : "+f"(c[0]), "+f"(c[1]), "+f"(c[2]), "+f"(c[3])
        : "r"(a[0]), "r"(a[1]), "r"(a[2]), "r"(a[3]), "r"(b[0]), "r"(b[1]));
}

// ------------------------------- MMA GEMM ----------------------------------
// All modes: C[128x128] = A[128,K] @ B[128,K]^T, bf16 split (AhBh+AhBl+AlBh).
// 3-stage cp.async pipeline; kk-level fragment double-buffering. (round-4 cfg)
#define STAGE_BYTES 65536
#define DSMEM_BYTES (3 * STAGE_BYTES + 1024)

struct Frags {
    uint32_t ah[4][4];
    uint32_t al[4][4];
    uint32_t bh[2][4];
    uint32_t bl[2][4];
};

template <int MODE>
__global__ __launch_bounds__(256, 1) void mma_k(const unsigned char* __restrict__ mask8) {
    extern __shared__ char dsm_raw[];
    const int tid = threadIdx.x;
    const int lane = tid & 31, wid = tid >> 5;
    const int wm = wid >> 2, wn = wid & 3;           // warp grid 2(m) x 4(n)
    const int col0 = blockIdx.x * 128, row0 = blockIdx.y * 128, z = blockIdx.z;

    const bf16 *pAh, *pAl, *pBh, *pBl;
    int ld, S, head = 0, bb = 0;
    if constexpr (MODE == 0) {
        ld = ATTP; S = ATTP / 64;
        pAh = g_xatt_hi + (size_t)row0 * ld; pAl = g_xatt_lo + (size_t)row0 * ld;
        pBh = g_U_hi   + (size_t)col0 * ld; pBl = g_U_lo   + (size_t)col0 * ld;
    } else if constexpr (MODE == 1) {
        head = z >> 5; bb = z & 31; ld = ND3; S = 4;
        size_t a0 = (size_t)(bb * 512 + row0) * ND3 + head * 256;
        size_t b0 = (size_t)(16384 + bb * 512 + col0) * ND3 + head * 256;
        pAh = g_r_hi + a0; pAl = g_r_lo + a0;
        pBh = g_r_hi + b0; pBl = g_r_lo + b0;
    } else if constexpr (MODE == 2) {
        head = z >> 5; bb = z & 31; ld = 512; S = 8;
        size_t a0 = (size_t)z * 262144 + (size_t)row0 * 512;
        size_t b0 = (size_t)z * 262144 + (size_t)col0 * 512;
        pAh = g_al_hi + a0; pAl = g_al_lo + a0;
        pBh = g_x3t_hi + b0; pBl = g_x3t_lo + b0;
    } else {
        ld = RNNIN; S = RNNIN / 64;
        pAh = g_x1_hi + (size_t)row0 * ld; pAl = g_x1_lo + (size_t)row0 * ld;
        pBh = g_W_hi + (size_t)col0 * ld;  pBl = g_W_lo + (size_t)col0 * ld;
    }

    const uint32_t sb = (smem_u32(dsm_raw) + 1023u) & ~1023u;

    float acc[4][4][4];
    #pragma unroll
    for (int i = 0; i < 4; i++)
        #pragma unroll
        for (int j = 0; j < 4; j++)
            #pragma unroll
            for (int q = 0; q < 4; q++) acc[i][j][q] = 0.f;

    const int a_row16 = lane & 15, a_half = lane >> 4;
    const int b_nrow  = (lane & 7) + ((lane >> 4) & 1) * 8;
    const int b_half  = (lane >> 3) & 1;

    #define ISSUE_STAGE(s)                                                         \
        do {                                                                       \
            const uint32_t sbase_ = sb + ((s) % 3) * STAGE_BYTES;                  \
            _Pragma("unroll")                                                      \
            for (int i = 0; i < 16; i++) {                                         \
                const int arr = i >> 2;                                            \
                const int idx = ((i & 3) << 8) + tid;                              \
                const int row = idx >> 3, u = idx & 7;                             \
                const bf16* p = (arr == 0) ? pAh : (arr == 1) ? pAl                \
                               : (arr == 2) ? pBh : pBl;                           \
                cp16(sbase_ + (arr << 14) + (row << 7) + ((u ^ (row & 7)) << 4),   \
                     p + (size_t)row * ld + (size_t)(s) * 64 + u * 8);             \
            }                                                                      \
            asm volatile("cp.async.commit_group;" ::: "memory");                   \
        } while (0)

    #define LOAD_FRAGS(f, kk)                                                      \
        do {                                                                       \
            _Pragma("unroll")                                                      \
            for (int np = 0; np < 2; np++) {                                       \
                const int nr = wn * 32 + np * 16 + b_nrow;                         \
                const int u = (kk) * 2 + b_half;                                   \
                const uint32_t off = (nr << 7) + ((u ^ (nr & 7)) << 4);            \
                ldsm4((f).bh[np], sBh + off);                                      \
                ldsm4((f).bl[np], sBl + off);                                      \
            }                                                                      \
            _Pragma("unroll")                                                      \
            for (int mt = 0; mt < 4; mt++) {                                       \
                const int row = wm * 64 + mt * 16 + a_row16;                       \
                const int u = (kk) * 2 + a_half;                                   \
                const uint32_t off = (row << 7) + ((u ^ (row & 7)) << 4);           \
                ldsm4((f).ah[mt], sAh + off);                                      \
                ldsm4((f).al[mt], sAl + off);                                      \
            }                                                                      \
        } while (0)

    ISSUE_STAGE(0);
    ISSUE_STAGE(1);
    Frags fr[2];
    for (int s = 0; s < S; s++) {
        if (s + 2 <= S) asm volatile("cp.async.wait_group 1;" ::: "memory");
        else            asm volatile("cp.async.wait_group 0;" ::: "memory");
        __syncthreads();
        if (s + 2 < S) ISSUE_STAGE(s + 2);

        const uint32_t sbase = sb + (s % 3) * STAGE_BYTES;
        const uint32_t sAh = sbase, sAl = sbase + 16384;
        const uint32_t sBh = sbase + 32768, sBl = sbase + 49152;

        LOAD_FRAGS(fr[0], 0);
        #pragma unroll
        for (int kk = 0; kk < 4; kk++) {
            Frags& f = fr[kk & 1];
            if (kk < 3) LOAD_FRAGS(fr[(kk + 1) & 1], kk + 1);
            #pragma unroll
            for (int mt = 0; mt < 4; mt++)
                #pragma unroll
                for (int nt = 0; nt < 4; nt++) {
                    const uint32_t* B2h = &f.bh[nt >> 1][(nt & 1) * 2];
                    const uint32_t* B2l = &f.bl[nt >> 1][(nt & 1) * 2];
                    mma16816(acc[mt][nt], f.ah[mt], B2h);
                    mma16816(acc[mt][nt], f.ah[mt], B2l);
                    mma16816(acc[mt][nt], f.al[mt], B2h);
                }
        }
    }
    #undef ISSUE_STAGE
    #undef LOAD_FRAGS

    // ----------------------------- epilogue --------------------------------
    #pragma unroll
    for (int mt = 0; mt < 4; mt++) {
        #pragma unroll
        for (int nt = 0; nt < 4; nt++) {
            const int mA = row0 + wm * 64 + mt * 16 + (lane >> 2);
            const int mB = mA + 8;
            const int nloc = col0 + wn * 32 + nt * 8 + (lane & 3) * 2;
            const float* c = acc[mt][nt];
            if constexpr (MODE == 0) {
                const bool isx2 = (row0 >= 16384);
                const float dv0 = isx2 ? g_dvec[nloc] : 1.f;
                const float dv1 = isx2 ? g_dvec[nloc + 1] : 1.f;
                #pragma unroll
                for (int half = 0; half < 2; half++) {
                    const int m = half ? mB : mA;
                    float v0 = fmaxf(c[half * 2 + 0], 0.f) * dv0;
                    float v1 = fmaxf(c[half * 2 + 1], 0.f) * dv1;
                    uint32_t H, L;
                    bsplit2pack(v0, v1, H, L);
                    *reinterpret_cast<uint32_t*>(g_r_hi + (size_t)m * ND3 + nloc) = H;
                    *reinterpret_cast<uint32_t*>(g_r_lo + (size_t)m * ND3 + nloc) = L;
                }
            } else if constexpr (MODE == 1) {
                const bool m0k = mask8[(size_t)bb * 512 + nloc] != 0;
                const bool m1k = mask8[(size_t)bb * 512 + nloc + 1] != 0;
                #pragma unroll
                for (int half = 0; half < 2; half++) {
                    const int m = half ? mB : mA;
                    float2 v;
                    v.x = m0k ? -1e30f : c[half * 2 + 0];
                    v.y = m1k ? -1e30f : c[half * 2 + 1];
                    *reinterpret_cast<float2*>(g_scores + (size_t)z * 262144 +
                                               (size_t)m * 512 + nloc) = v;
                }
            } else if constexpr (MODE == 2) {
                #pragma unroll
                for (int half = 0; half < 2; half++) {
                    const int m = half ? mB : mA;
                    uint32_t H, L;
                    bsplit2pack(c[half * 2 + 0], c[half * 2 + 1], H, L);
                    size_t o = (size_t)(bb * 512 + m) * RNNIN + 1024 + head * 512 + nloc;
                    *reinterpret_cast<uint32_t*>(g_x1_hi + o) = H;
                    *reinterpret_cast<uint32_t*>(g_x1_lo + o) = L;
                }
            } else {
                const float b0 = g_bias[nloc], b1 = g_bias[nloc + 1];
                #pragma unroll
                for (int half = 0; half < 2; half++) {
                    const int m = half ? mB : mA;
                    float2 v;
                    v.x = c[half * 2 + 0] + b0;
                    v.y = c[half * 2 + 1] + b1;
                    *reinterpret_cast<float2*>(g_gates + (size_t)m * NGATE + nloc) = v;
                }
            }
        }
    }
}

// ------------------------------ softmax ------------------------------------
__global__ void softmax_k() {
    const float* p = g_scores + (size_t)blockIdx.x * 512;
    bf16* oh = g_al_hi + (size_t)blockIdx.x * 512;
    bf16* ol = g_al_lo + (size_t)blockIdx.x * 512;
    const int t = threadIdx.x;  // 128 threads * 4 = 512
    float4 v = reinterpret_cast<const float4*>(p)[t];
    float mx = fmaxf(fmaxf(v.x, v.y), fmaxf(v.z, v.w));
    #pragma unroll
    for (int o = 16; o; o >>= 1) mx = fmaxf(mx, __shfl_xor_sync(0xffffffffu, mx, o));
    __shared__ float red[4], red2[4];
    if ((t & 31) == 0) red[t >> 5] = mx;
    __syncthreads();
    mx = fmaxf(fmaxf(red[0], red[1]), fmaxf(red[2], red[3]));
    v.x = __expf(v.x - mx); v.y = __expf(v.y - mx);
    v.z = __expf(v.z - mx); v.w = __expf(v.w - mx);
    float s = v.x + v.y + v.z + v.w;
    #pragma unroll
    for (int o = 16; o; o >>= 1) s += __shfl_xor_sync(0xffffffffu, s, o);
    if ((t & 31) == 0) red2[t >> 5] = s;
    __syncthreads();
    s = red2[0] + red2[1] + red2[2] + red2[3];
    float inv = 1.f / s;
    v.x *= inv; v.y *= inv; v.z *= inv; v.w *= inv;
    uint32_t H0, L0, H1, L1;
    bsplit2pack(v.x, v.y, H0, L0);
    bsplit2pack(v.z, v.w, H1, L1);
    reinterpret_cast<uint32_t*>(oh)[t * 2]     = H0;
    reinterpret_cast<uint32_t*>(oh)[t * 2 + 1] = H1;
    reinterpret_cast<uint32_t*>(ol)[t * 2]     = L0;
    reinterpret_cast<uint32_t*>(ol)[t * 2 + 1] = L1;
}

// ------------------------------- LSTM (HMMA) --------------------------------
// 128 CTAs: dir = blk>>6, u0 = (blk&63)*4 (16 gate rows = M16).
// Per step: z[16x32] = Whh_slice[16x256] . h[32x256]^T on HMMA, bf16 3-term.
// 8 warps k-split (k32 each), fp32 partials reduced through smem.
#define LROW 264                      // padded bf16 row (256+8)
#define LROWB (LROW * 2)              // 528 bytes
// smem (floats): Ws_hi/lo 16*264 bf16 each, h_hi/lo 32*264 bf16 each,
// zpart 8*16*32 f32, z_s 16*33 f32, s_out 128 f32, s_hh/s_hl 128 bf16 each
#define LSTM_SMEM (16*LROW*2*2 + 32*LROW*2*2 + 8*16*32*4 + 16*33*4 + 128*4 + 128*2*2 + 64)

__device__ __forceinline__ float sigmf_(float x) { return 1.f / (1.f + __expf(-x)); }
__device__ __forceinline__ float tanhf_(float x) { return 2.f / (1.f + __expf(-2.f * x)) - 1.f; }

__global__ __launch_bounds__(256, 1) void lstm_k(float* __restrict__ out,
                                                 const float* __restrict__ Whh_f,
                                                 const float* __restrict__ Whh_b) {
    extern __shared__ char lraw[];
    bf16*  Ws_hi = (bf16*)lraw;                 // [16][LROW]
    bf16*  Ws_lo = Ws_hi + 16 * LROW;
    bf16*  h_hi  = Ws_lo + 16 * LROW;           // [32][LROW]
    bf16*  h_lo  = h_hi + 32 * LROW;
    float* zpart = (float*)(h_lo + 32 * LROW);  // [8][16][32]
    float* z_s   = zpart + 8 * 16 * 32;         // [16][33]
    float* s_out = z_s + 16 * 33;               // [32][4]
    bf16*  s_hh  = (bf16*)(s_out + 128);        // [32][4]
    bf16*  s_hl  = s_hh + 128;
    __shared__ unsigned base_s;

    const int tid = threadIdx.x;
    const int lane = tid & 31, w = tid >> 5;
    const int blk = blockIdx.x;
    const int dir = blk >> 6;
    const int u0  = (blk & 63) * 4;

    const uint32_t ws_hi_a = smem_u32(Ws_hi), ws_lo_a = smem_u32(Ws_lo);
    const uint32_t h_hi_a  = smem_u32(h_hi),  h_lo_a  = smem_u32(h_lo);

    // ---- load + split Whh slice: 16 rows x 256 ----
    {
        const int zl = tid >> 4, c16 = (tid & 15) * 16;
        const int grow = (zl >> 2) * 256 + u0 + (zl & 3);
        const float* src = (dir ? Whh_b : Whh_f) + (size_t)grow * 256 + c16;
        #pragma unroll
        for (int i = 0; i < 4; i++) {
            float4 v = *reinterpret_cast<const float4*>(src + i * 4);
            uint2 H, L;
            bsplit2pack(v.x, v.y, H.x, L.x);
            bsplit2pack(v.z, v.w, H.y, L.y);
            *reinterpret_cast<uint2*>(&Ws_hi[zl * LROW + c16 + i * 4]) = H;
            *reinterpret_cast<uint2*>(&Ws_lo[zl * LROW + c16 + i * 4]) = L;
        }
    }
    if (tid == 0) base_s = *((volatile unsigned*)&g_release);
    __syncthreads();
    const unsigned base = base_s;

    // frag-lane constants (same proven patterns as mma_k)
    const int a_row16 = lane & 15, a_half = lane >> 4;
    const int b_nrow  = (lane & 7) + ((lane >> 4) & 1) * 8;
    const int b_half  = (lane >> 3) & 1;

    // reduction role: 2 elements (rzl, rb), (rzl, rb+1)
    const int rzl = tid >> 4, rb = (tid & 15) * 2;
    const int rcol = dir * 1024 + (rzl >> 2) * 256 + u0 + (rzl & 3);

    // pointwise role (tid < 128): unit j, batch b
    const int pj = tid >> 5, pb = tid & 31;

    float c_reg = 0.f;
    int cur = 0;
    int tt0 = dir ? 511 : 0;
    float gate0 = g_gates[(size_t)(rb * 512 + tt0) * NGATE + rcol];
    float gate1 = g_gates[(size_t)((rb + 1) * 512 + tt0) * NGATE + rcol];

    for (int s = 0; s < 512; s++) {
        const int tt = dir ? (511 - s) : s;

        // ---- load h (bf16 hi/lo) from global into padded smem ----
        const bf16* ghh = &g_hh[cur][dir][0][0];
        const bf16* ghl = &g_hl[cur][dir][0][0];
        #pragma unroll
        for (int i = 0; i < 4; i++) {
            int u8 = tid + 256 * i;              // 1024 chunks of 8 bf16
            int row = u8 >> 5, k8 = u8 & 31;
            uint4 vh = *reinterpret_cast<const uint4*>(ghh + row * 256 + k8 * 8);
            uint4 vl = *reinterpret_cast<const uint4*>(ghl + row * 256 + k8 * 8);
            *reinterpret_cast<uint4*>(&h_hi[row * LROW + k8 * 8]) = vh;
            *reinterpret_cast<uint4*>(&h_lo[row * LROW + k8 * 8]) = vl;
        }
        __syncthreads();

        // ---- HMMA: z[16x32] partial for this warp's k32 slice ----
        {
            uint32_t ah[2][4], al[2][4], bh2[2][2][4], bl2[2][2][4];
            #pragma unroll
            for (int kk = 0; kk < 2; kk++) {
                const uint32_t aoff = (uint32_t)(a_row16 * LROWB + w * 64 + kk * 32 + a_half * 16);
                ldsm4(ah[kk], ws_hi_a + aoff);
                ldsm4(al[kk], ws_lo_a + aoff);
            }
            #pragma unroll
            for (int np = 0; np < 2; np++)
                #pragma unroll
                for (int kk = 0; kk < 2; kk++) {
                    const uint32_t boff =
                        (uint32_t)((np * 16 + b_nrow) * LROWB + w * 64 + kk * 32 + b_half * 16);
                    ldsm4(bh2[np][kk], h_hi_a + boff);
                    ldsm4(bl2[np][kk], h_lo_a + boff);
                }
            float acc[4][4];
            #pragma unroll
            for (int nt = 0; nt < 4; nt++)
                #pragma unroll
                for (int q = 0; q < 4; q++) acc[nt][q] = 0.f;
            #pragma unroll
            for (int kk = 0; kk < 2; kk++)
                #pragma unroll
                for (int nt = 0; nt < 4; nt++) {
                    const uint32_t* Bh = &bh2[nt >> 1][kk][(nt & 1) * 2];
                    const uint32_t* Bl = &bl2[nt >> 1][kk][(nt & 1) * 2];
                    mma16816(acc[nt], ah[kk], Bh);
                    mma16816(acc[nt], ah[kk], Bl);
                    mma16816(acc[nt], al[kk], Bh);
                }
            const int r = lane >> 2;
            #pragma unroll
            for (int nt = 0; nt < 4; nt++) {
                const int ct = nt * 8 + (lane & 3) * 2;
                *reinterpret_cast<float2*>(&zpart[(w * 16 + r) * 32 + ct]) =
                    make_float2(acc[nt][0], acc[nt][1]);
                *reinterpret_cast<float2*>(&zpart[(w * 16 + r + 8) * 32 + ct]) =
                    make_float2(acc[nt][2], acc[nt][3]);
            }
        }
        __syncthreads();

        // ---- reduce partials + gate input ----
        {
            float z0 = gate0, z1 = gate1;
            #pragma unroll
            for (int w2 = 0; w2 < 8; w2++) {
                float2 p = *reinterpret_cast<const float2*>(&zpart[(w2 * 16 + rzl) * 32 + rb]);
                z0 += p.x; z1 += p.y;
            }
            z_s[rzl * 33 + rb]     = z0;
            z_s[rzl * 33 + rb + 1] = z1;
        }
        __syncthreads();

        // ---- pointwise cell ----
        if (tid < 128) {
            float zi = z_s[(0 + pj) * 33 + pb];
            float zf = z_s[(4 + pj) * 33 + pb];
            float zg = z_s[(8 + pj) * 33 + pb];
            float zo = z_s[(12 + pj) * 33 + pb];
            c_reg = sigmf_(zf) * c_reg + sigmf_(zi) * tanhf_(zg);
            float hval = sigmf_(zo) * tanhf_(c_reg);
            s_out[pb * 4 + pj] = hval;
            bf16 hh, hl;
            bsplit(hval, hh, hl);
            s_hh[pb * 4 + pj] = hh;
            s_hl[pb * 4 + pj] = hl;
        }
        __syncthreads();

        // ---- publish h(s+1) (coalesced-ish 8B stores) ----
        if (tid < 32) {
            uint2 vh = *reinterpret_cast<const uint2*>(&s_hh[tid * 4]);
            uint2 vl = *reinterpret_cast<const uint2*>(&s_hl[tid * 4]);
            *reinterpret_cast<uint2*>(&g_hh[cur ^ 1][dir][tid][u0]) = vh;
            *reinterpret_cast<uint2*>(&g_hl[cur ^ 1][dir][tid][u0]) = vl;
        }
        __syncthreads();

        // ---- barrier arrive ----
        const unsigned target = base + (unsigned)s + 1u;
        bool is_setter = false;
        if (tid == 0) {
            __threadfence();
            unsigned old = atomicAdd(&g_count, 1u);
            is_setter = (old == target * LSTM_NB - 1u);
        }

        // overlapped with barrier propagation: out store (16B) + gate prefetch
        if (tid < 32)
            *reinterpret_cast<float4*>(&out[(size_t)(tid * 512 + tt) * 512 + dir * 256 + u0]) =
                *reinterpret_cast<const float4*>(&s_out[tid * 4]);
        if (s + 1 < 512) {
            const int ttn = dir ? (511 - (s + 1)) : (s + 1);
            gate0 = g_gates[(size_t)(rb * 512 + ttn) * NGATE + rcol];
            gate1 = g_gates[(size_t)((rb + 1) * 512 + ttn) * NGATE + rcol];
        }

        // ---- barrier wait ----
        if (tid == 0) {
            if (is_setter) {
                __threadfence();
                *((volatile unsigned*)&g_release) = target;
            } else {
                while ((int)(*((volatile unsigned*)&g_release) - target) < 0) __nanosleep(32);
            }
            __threadfence();
        }
        __syncthreads();
        cur ^= 1;
    }
}

// ------------------------------ launch -------------------------------------
static inline int cdiv(int a, int b) { return (a + b - 1) / b; }

extern "C" void kernel_launch(void* const* d_in, const int* in_sizes, int n_in,
                              void* d_out, int out_size) {
    (void)in_sizes; (void)n_in; (void)out_size;
    const float* x1w  = (const float*)d_in[0];
    const float* x1a0 = (const float*)d_in[1];
    const float* x1a1 = (const float*)d_in[2];
    const float* x2w  = (const float*)d_in[3];
    const float* x2a0 = (const float*)d_in[4];
    const float* x2a1 = (const float*)d_in[5];
    const float* x2a2 = (const float*)d_in[6];
    const unsigned char* x2mask = (const unsigned char*)d_in[8];
    const float* U0 = (const float*)d_in[9];
    const float* d0 = (const float*)d_in[10];
    const float* U1 = (const float*)d_in[11];
    const float* d1 = (const float*)d_in[12];
    const float* U2 = (const float*)d_in[13];
    const float* d2 = (const float*)d_in[14];
    const float* Wihf = (const float*)d_in[15];
    const float* Whhf = (const float*)d_in[16];
    const float* bihf = (const float*)d_in[17];
    const float* bhhf = (const float*)d_in[18];
    const float* Wihb = (const float*)d_in[19];
    const float* Whhb = (const float*)d_in[20];
    const float* bihb = (const float*)d_in[21];
    const float* bhhb = (const float*)d_in[22];
    float* out = (float*)d_out;

    cudaFuncSetAttribute(mma_k<0>, cudaFuncAttributeMaxDynamicSharedMemorySize, DSMEM_BYTES);
    cudaFuncSetAttribute(mma_k<1>, cudaFuncAttributeMaxDynamicSharedMemorySize, DSMEM_BYTES);
    cudaFuncSetAttribute(mma_k<2>, cudaFuncAttributeMaxDynamicSharedMemorySize, DSMEM_BYTES);
    cudaFuncSetAttribute(mma_k<3>, cudaFuncAttributeMaxDynamicSharedMemorySize, DSMEM_BYTES);
    cudaFuncSetAttribute(lstm_k, cudaFuncAttributeMaxDynamicSharedMemorySize, LSTM_SMEM);

    // launch order tuned so ncu (-s 5 => our launch index 3) captures mma_k<0>
    k_build_xatt<<<cdiv(2 * NB * LL * (ATTP / 4), 256), 256>>>(x1w, x1a0, x1a1, x2w, x2a0, x2a1);
    k_build_U<<<cdiv(ND3 * (ATTP / 4), 256), 256>>>(U0, U1, U2);
    k_build_dvec<<<cdiv(ND3, 256), 256>>>(d0, d1, d2);
    // r = relu(xatt @ U^T): M=32768, N=768, K=1344
    mma_k<0><<<dim3(ND3 / 128, 256, 1), 256, DSMEM_BYTES>>>(nullptr);

    k_build_W<<<cdiv(NGATE * (RNNIN / 4), 256), 256>>>(Wihf, Wihb);
    k_build_bias<<<cdiv(NGATE, 256), 256>>>(bihf, bhhf, bihb, bhhb);
    k_build_x1head<<<cdiv(NB * LL * 256, 256), 256>>>(x1a0, x1a1);
    k_zero_h<<<cdiv(2 * 2 * NB * HID, 256), 256>>>();
    k_x3t<<<dim3(16, 8, 96), dim3(32, 8)>>>(x2a0, x2a1, x2a2);

    // scores per (head,b): 512x512x256
    mma_k<1><<<dim3(4, 4, 96), 256, DSMEM_BYTES>>>(x2mask);
    softmax_k<<<3 * NB * LL, 128>>>();
    // attn = alpha @ x3t^T: 512x512x512 per (head,b)
    mma_k<2><<<dim3(4, 4, 96), 256, DSMEM_BYTES>>>(nullptr);
    // gates = x1 @ W^T + bias: M=16384, N=2048, K=2560
    mma_k<3><<<dim3(NGATE / 128, 128, 1), 256, DSMEM_BYTES>>>(nullptr);
    // BiLSTM recurrence (HMMA z-GEMM)
    lstm_k<<<LSTM_NB, 256, LSTM_SMEM>>>(out, Whhf, Whhb);
}